// round 2
// baseline (speedup 1.0000x reference)
#include <cuda_runtime.h>
#include <cstdint>

// LBP semantic dependency, difference-space reformulation.
// B=2, S=160. One 2-CTA cluster per (i, b) problem; pair-parity split of the
// d[j,k] message-difference state so transpose partners stay CTA-local.

#define S   160
#define S2  25600
#define S3  4096000
#define BQ  2
#define NTHREADS 640
#define DPITCH 81            // row pitch for d (odd -> conflict-free strided STS)
#define LOG2E 1.4426950408889634f

// shared memory layout (in floats)
#define OFF_D    0                        // d[3][160][81]
#define OFF_DB   (3*S*DPITCH)             // deltab[160]
#define OFF_ACC  (OFF_DB + S)             // local row-sum partials
#define OFF_ACCP (OFF_ACC + S)            // peer row-sum partials (pushed by peer)
#define OFF_W    (OFF_ACCP + S)           // w[k] = mask[b,k,i] * (k!=i)
#define OFF_MJ   (OFF_W + S)              // mj[j] = mask[b,j,i]
#define OFF_SE   (OFF_MJ + S)             // s_edge[b,j,i] * log2(e)
#define SMEM_FLOATS (OFF_SE + S)
#define SMEM_BYTES  (SMEM_FLOATS * 4)

extern __shared__ float sm[];

__device__ __forceinline__ uint32_t smem_u32(const void* p) {
    uint32_t a;
    asm("{ .reg .u64 t; cvta.to.shared.u64 t, %1; cvt.u32.u64 %0, t; }"
        : "=r"(a) : "l"(p));
    return a;
}
__device__ __forceinline__ void cluster_sync_() {
    asm volatile("barrier.cluster.arrive.aligned;" ::: "memory");
    asm volatile("barrier.cluster.wait.aligned;" ::: "memory");
}
__device__ __forceinline__ void st_remote_f32(uint32_t laddr, uint32_t rank, float v) {
    asm volatile(
        "{ .reg .b32 r; mapa.shared::cluster.u32 r, %0, %1; "
        "st.shared::cluster.f32 [r], %2; }"
        :: "r"(laddr), "r"(rank), "f"(v) : "memory");
}
__device__ __forceinline__ float ex2f_(float x) {
    float y; asm("ex2.approx.ftz.f32 %0, %1;" : "=f"(y) : "f"(x)); return y;
}
__device__ __forceinline__ float lg2f_(float x) {
    float y; asm("lg2.approx.ftz.f32 %0, %1;" : "=f"(y) : "f"(x)); return y;
}
// softplus base-2: log2(1 + 2^x), numerically stable for all x
__device__ __forceinline__ float sp2(float x) {
    float e = ex2f_(-fabsf(x));            // in (0,1]
    return fmaxf(x, 0.f) + lg2f_(1.f + e); // lg2 arg in [1,2] -> high accuracy
}

// dtype-agnostic mask read: the harness may store the JAX bool mask as
// 1-byte bools, int32, or float32. Probe word 0 once: 0x01010101 can only be
// four true bytes; otherwise treat elements as 32-bit words (nonzero = true).
__device__ __forceinline__ bool mask_at(const void* m, bool byteMask, int idx) {
    if (byteMask) return ((const unsigned char*)m)[idx] != 0;
    return ((const uint32_t*)m)[idx] != 0u;
}

__global__ void __launch_bounds__(NTHREADS, 1) __cluster_dims__(2, 1, 1)
lbp_kernel(const float* __restrict__ s_edge,
           const float* __restrict__ s_sib,
           const float* __restrict__ s_cop,
           const float* __restrict__ s_grd,
           const void* __restrict__ mask,
           float* __restrict__ out)
{
    const int tid  = threadIdx.x;
    const int blk  = blockIdx.x;
    const int c    = blk & 1;        // cluster rank == pair-parity class
    const int prob = blk >> 1;       // problem id
    const int i    = prob % S;
    const int b    = prob / S;

    const int w  = tid >> 5;
    const int l  = tid & 31;
    const int jb = w % 5;            // j block (5 x 32 = 160)
    const int q  = w / 5;            // kk quarter (4 x 20 = 80)
    const int j  = jb * 32 + l;
    const int par = (c ^ (j & 1));   // k = 2*kk + par  satisfies (j+k)&1 == c

    const bool byteMask = (*(const uint32_t*)mask == 0x01010101u);

    // ---- init shared state ----
    for (int x = tid; x < 3 * S * DPITCH; x += NTHREADS) sm[OFF_D + x] = 0.f;
    if (tid < S) {
        const int k = tid;
        const bool mk = mask_at(mask, byteMask, b * S2 + k * S + i);
        const float mf = mk ? 1.f : 0.f;
        sm[OFF_W   + k] = (mk && (k != i)) ? 1.f : 0.f;
        sm[OFF_MJ  + k] = mf;
        sm[OFF_SE  + k] = s_edge[b * S2 + k * S + i] * LOG2E;
        sm[OFF_DB  + k] = 0.f;
        sm[OFF_ACC + k] = 0.f;
        sm[OFF_ACCP+ k] = 0.f;
    }
    __syncthreads();
    cluster_sync_();   // peer smem fully initialized before any remote stores

    const float* Ps[3] = { s_sib + (size_t)b * S3,
                           s_cop + (size_t)b * S3,
                           s_grd + (size_t)b * S3 };

    const uint32_t accpAddr = smem_u32(sm + OFF_ACCP);
    const uint32_t peer = (uint32_t)(c ^ 1);

    for (int it = 0; it < 3; ++it) {
        float rowsum = 0.f;  // sum over this thread's (k) of w[k]*(k!=j)*D, all 3 types

        #pragma unroll
        for (int t = 0; t < 3; ++t) {
            const float* __restrict__ P = Ps[t];
            float* __restrict__ dbase = sm + OFF_D + t * S * DPITCH;

            // Phase R: stage d_old[k][j] (transpose partner) + p[i,k,j] in regs
            float dreg[20], preg[20];
            #pragma unroll
            for (int u = 0; u < 20; ++u) {
                const int kk = q * 20 + u;
                const int k  = 2 * kk + par;
                dreg[u] = dbase[k * DPITCH + (j >> 1)];
                preg[u] = P[k * S2 + i * S + j];
            }
            __syncthreads();   // all reads of d[t] before any writes of d[t]

            // Phase W: compute new message differences, write in place
            #pragma unroll
            for (int u = 0; u < 20; ++u) {
                const int kk = q * 20 + u;
                const int k  = 2 * kk + par;
                const float delt = sm[OFF_DB + k] - dreg[u];
                const float p2   = preg[u] * LOG2E;
                const float D    = sp2(delt + p2) - sp2(delt);
                dbase[j * DPITCH + kk] = D;
                rowsum += (k != j) ? sm[OFF_W + k] * D : 0.f;
            }
            // no barrier needed between types: disjoint d arrays
        }

        // ---- belief update: Δb[j] = se2[j] + mj[j] * Σ_k (masked) Σ_t d[j,k] ----
        atomicAdd(&sm[OFF_ACC + j], rowsum);
        __syncthreads();
        if (tid < S) st_remote_f32(accpAddr + 4u * (uint32_t)tid, peer, sm[OFF_ACC + tid]);
        cluster_sync_();   // peer partials landed
        if (tid < S) {
            const float tot = sm[OFF_ACC + tid] + sm[OFF_ACCP + tid];
            sm[OFF_DB + tid] = sm[OFF_SE + tid] + sm[OFF_MJ + tid] * tot;
            sm[OFF_ACC + tid] = 0.f;
        }
        cluster_sync_();   // accp consumed before peer's next push; Δb visible
        __syncthreads();
    }

    // ---- output: out[b, j, i, c] = softmax over channels (base-2 domain) ----
    if (c == 0 && tid < S) {
        const float D  = sm[OFF_DB + tid];
        const float e  = ex2f_(-fabsf(D));     // 2^{-|Δb|} in (0,1]
        const float pb = 1.f / (1.f + e);      // prob of the larger channel
        const float ps = e * pb;               // prob of the smaller channel
        const float p1 = (D >= 0.f) ? pb : ps;
        const float p0 = (D >= 0.f) ? ps : pb;
        float* o = out + ((size_t)((b * S + tid) * S + i)) * 2;
        o[0] = p0;
        o[1] = p1;
    }
}

extern "C" void kernel_launch(void* const* d_in, const int* in_sizes, int n_in,
                              void* d_out, int out_size) {
    (void)in_sizes; (void)n_in; (void)out_size;
    cudaFuncSetAttribute(lbp_kernel,
                         cudaFuncAttributeMaxDynamicSharedMemorySize, SMEM_BYTES);
    const float* s_edge = (const float*)d_in[0];
    const float* s_sib  = (const float*)d_in[1];
    const float* s_cop  = (const float*)d_in[2];
    const float* s_grd  = (const float*)d_in[3];
    const void*  mask   = d_in[4];
    float* outp = (float*)d_out;

    lbp_kernel<<<BQ * S * 2, NTHREADS, SMEM_BYTES>>>(
        s_edge, s_sib, s_cop, s_grd, mask, outp);
}